// round 2
// baseline (speedup 1.0000x reference)
#include <cuda_runtime.h>
#include <cuda_bf16.h>
#include <math.h>

#define N_ENT  50000
#define N_REL  16
#define N_EDGE 1000000
#define DOUT_TOTAL 176

// ---------------- scratch (static device allocations) ----------------
__device__ float g_proj[(size_t)N_REL * N_ENT * 64];   // 204.8 MB
__device__ float g_att[N_EDGE];
__device__ float g_a[N_EDGE];
__device__ int   g_deg[N_ENT];
__device__ int   g_incl[N_ENT];
__device__ int   g_offs[N_ENT + 1];
__device__ int   g_cursor[N_ENT];
__device__ int   g_bsum[256];
__device__ int   g_esort[N_EDGE];
__device__ float g_h1[(size_t)N_ENT * 64];
__device__ float g_h2[(size_t)N_ENT * 32];
__device__ float g_h3[(size_t)N_ENT * 16];
__device__ float g_Nh[(size_t)N_ENT * 64];

// ---------------- init ----------------
__global__ __launch_bounds__(256) void k_zero() {
    int i = blockIdx.x * blockDim.x + threadIdx.x;
    if (i < N_ENT) { g_deg[i] = 0; g_cursor[i] = 0; }
}

// ---------------- proj[r,n,e] = sum_d ent[n,d] * W_R[r,d,e] ----------------
// block: 256 threads = 64 cols x 4 node-groups; tile = 64 nodes, 1 relation.
__global__ __launch_bounds__(256) void k_proj(const float* __restrict__ ent,
                                              const float* __restrict__ WR) {
    __shared__ __align__(16) float Wsm[64 * 64];
    __shared__ __align__(16) float entT[64 * 68];   // [k][node], pitch 68
    const int r  = blockIdx.y;
    const int n0 = blockIdx.x * 64;
    const int tid = threadIdx.x;

    const float* W = WR + (size_t)r * 4096;
    for (int i = tid; i < 4096; i += 256) Wsm[i] = W[i];
    for (int i = tid; i < 4096; i += 256) {
        int node = i >> 6, k = i & 63;
        int n = n0 + node;
        entT[k * 68 + node] = (n < N_ENT) ? ent[(size_t)n * 64 + k] : 0.0f;
    }
    __syncthreads();

    const int d = tid & 63;       // output column e
    const int g = tid >> 6;       // node group (16 nodes)
    float acc[16];
#pragma unroll
    for (int i = 0; i < 16; i++) acc[i] = 0.0f;

#pragma unroll 4
    for (int k = 0; k < 64; k++) {
        float w = Wsm[k * 64 + d];
        const float4* ep = reinterpret_cast<const float4*>(&entT[k * 68 + g * 16]);
        float4 e0 = ep[0], e1 = ep[1], e2 = ep[2], e3 = ep[3];
        acc[0]  += e0.x * w; acc[1]  += e0.y * w; acc[2]  += e0.z * w; acc[3]  += e0.w * w;
        acc[4]  += e1.x * w; acc[5]  += e1.y * w; acc[6]  += e1.z * w; acc[7]  += e1.w * w;
        acc[8]  += e2.x * w; acc[9]  += e2.y * w; acc[10] += e2.z * w; acc[11] += e2.w * w;
        acc[12] += e3.x * w; acc[13] += e3.y * w; acc[14] += e3.z * w; acc[15] += e3.w * w;
    }

    float* outb = g_proj + ((size_t)r * N_ENT + n0) * 64;
#pragma unroll
    for (int i = 0; i < 16; i++) {
        int node = g * 16 + i;
        if (n0 + node < N_ENT) outb[(size_t)node * 64 + d] = acc[i];
    }
}

// ---------------- per-edge attention logits (warp per edge) ----------------
__global__ __launch_bounds__(256) void k_att(const float* __restrict__ rel,
                                             const int* __restrict__ src,
                                             const int* __restrict__ dst,
                                             const int* __restrict__ et) {
    int w = (blockIdx.x * blockDim.x + threadIdx.x) >> 5;
    int lane = threadIdx.x & 31;
    if (w >= N_EDGE) return;
    int s = src[w], dv = dst[w], r = et[w];
    const float2* pt = reinterpret_cast<const float2*>(g_proj + ((size_t)r * N_ENT + s) * 64);
    const float2* ph = reinterpret_cast<const float2*>(g_proj + ((size_t)r * N_ENT + dv) * 64);
    const float2* pr = reinterpret_cast<const float2*>(rel + (size_t)r * 64);
    float2 t = pt[lane], h = ph[lane], rr = pr[lane];
    float p = t.x * tanhf(h.x + rr.x) + t.y * tanhf(h.y + rr.y);
#pragma unroll
    for (int o = 16; o; o >>= 1) p += __shfl_xor_sync(0xffffffffu, p, o);
    if (lane == 0) g_att[w] = p;
}

// ---------------- CSR build: histogram, scan, scatter ----------------
__global__ __launch_bounds__(256) void k_count(const int* __restrict__ dst) {
    int e = blockIdx.x * blockDim.x + threadIdx.x;
    if (e < N_EDGE) atomicAdd(&g_deg[dst[e]], 1);
}

__global__ __launch_bounds__(512) void k_scan1() {
    __shared__ int sm[512];
    int i = blockIdx.x * 512 + threadIdx.x;
    int v = (i < N_ENT) ? g_deg[i] : 0;
    sm[threadIdx.x] = v;
    __syncthreads();
    for (int off = 1; off < 512; off <<= 1) {
        int t = (threadIdx.x >= off) ? sm[threadIdx.x - off] : 0;
        __syncthreads();
        sm[threadIdx.x] += t;
        __syncthreads();
    }
    if (i < N_ENT) g_incl[i] = sm[threadIdx.x];
    if (threadIdx.x == 511) g_bsum[blockIdx.x] = sm[511];
}

__global__ void k_scan2(int nb) {
    if (blockIdx.x == 0 && threadIdx.x == 0) {
        int run = 0;
        for (int b = 0; b < nb; b++) { int t = g_bsum[b]; g_bsum[b] = run; run += t; }
    }
}

__global__ __launch_bounds__(512) void k_scan3() {
    int i = blockIdx.x * blockDim.x + threadIdx.x;
    if (i < N_ENT) g_offs[i] = g_incl[i] - g_deg[i] + g_bsum[i / 512];
    if (i == 0) g_offs[N_ENT] = N_EDGE;
}

__global__ __launch_bounds__(256) void k_scatter(const int* __restrict__ dst) {
    int e = blockIdx.x * blockDim.x + threadIdx.x;
    if (e < N_EDGE) {
        int d = dst[e];
        int pos = g_offs[d] + atomicAdd(&g_cursor[d], 1);
        g_esort[pos] = e;
    }
}

// ---------------- edge softmax grouped by dst (warp per node) ----------------
__global__ __launch_bounds__(256) void k_softmax() {
    int n = blockIdx.x * (blockDim.x >> 5) + (threadIdx.x >> 5);
    int lane = threadIdx.x & 31;
    if (n >= N_ENT) return;
    int beg = g_offs[n], end = g_offs[n + 1];
    if (beg == end) return;
    float m = -3.4e38f;
    for (int p = beg + lane; p < end; p += 32) m = fmaxf(m, g_att[g_esort[p]]);
#pragma unroll
    for (int o = 16; o; o >>= 1) m = fmaxf(m, __shfl_xor_sync(0xffffffffu, m, o));
    float s = 0.0f;
    for (int p = beg + lane; p < end; p += 32) s += expf(g_att[g_esort[p]] - m);
#pragma unroll
    for (int o = 16; o; o >>= 1) s += __shfl_xor_sync(0xffffffffu, s, o);
    float inv = 1.0f / s;
    for (int p = beg + lane; p < end; p += 32) {
        int e = g_esort[p];
        g_a[e] = expf(g_att[e] - m) * inv;
    }
}

// ---------------- aggregation: Nh[n] = sum_{e: dst=n} a[e]*h[src[e]] ----------------
template <int L>
__global__ __launch_bounds__(256) void k_agg(const float* __restrict__ ent,
                                             const int* __restrict__ src) {
    constexpr int DIN = (L == 0) ? 64 : (L == 1) ? 64 : 32;
    const float* h = (L == 0) ? ent : (L == 1) ? g_h1 : g_h2;
    int n = blockIdx.x * (blockDim.x >> 5) + (threadIdx.x >> 5);
    int lane = threadIdx.x & 31;
    if (n >= N_ENT) return;
    int beg = g_offs[n], end = g_offs[n + 1];
    constexpr int V = DIN / 32;
    float acc[V];
#pragma unroll
    for (int v = 0; v < V; v++) acc[v] = 0.0f;
    for (int p = beg; p < end; p++) {
        int e = g_esort[p];
        float c = g_a[e];
        const float* hs = h + (size_t)src[e] * DIN;
#pragma unroll
        for (int v = 0; v < V; v++) acc[v] += c * hs[lane + 32 * v];
    }
#pragma unroll
    for (int v = 0; v < V; v++) g_Nh[(size_t)n * DIN + lane + 32 * v] = acc[v];
}

// ---------------- layer transform: out = lrelu((h+Nh)W1+b1)+lrelu((h*Nh)W2+b2) ----------------
template <int L>
__global__ __launch_bounds__(256) void k_transform(const float* __restrict__ ent,
                                                   const float* __restrict__ W1,
                                                   const float* __restrict__ b1,
                                                   const float* __restrict__ W2,
                                                   const float* __restrict__ b2) {
    constexpr int DIN  = (L == 0) ? 64 : (L == 1) ? 64 : 32;
    constexpr int DOUT = (L == 0) ? 64 : (L == 1) ? 32 : 16;
    const float* h  = (L == 0) ? ent : (L == 1) ? g_h1 : g_h2;
    float* hout     = (L == 0) ? g_h1 : (L == 1) ? g_h2 : g_h3;

    __shared__ float W1s[DIN * DOUT], W2s[DIN * DOUT];
    __shared__ float b1s[DOUT], b2s[DOUT];
    for (int i = threadIdx.x; i < DIN * DOUT; i += blockDim.x) { W1s[i] = W1[i]; W2s[i] = W2[i]; }
    if (threadIdx.x < DOUT) { b1s[threadIdx.x] = b1[threadIdx.x]; b2s[threadIdx.x] = b2[threadIdx.x]; }
    __syncthreads();

    int lane = threadIdx.x & 31, wid = threadIdx.x >> 5;
    int wpb = blockDim.x >> 5;
    constexpr int V  = DIN / 32;
    constexpr int OV = (DOUT + 31) / 32;

    for (int n = blockIdx.x * wpb + wid; n < N_ENT; n += gridDim.x * wpb) {
        float hv[V], nv[V];
#pragma unroll
        for (int v = 0; v < V; v++) {
            int c = lane + 32 * v;
            hv[v] = h[(size_t)n * DIN + c];
            nv[v] = g_Nh[(size_t)n * DIN + c];
        }
        float a1[OV], a2[OV];
#pragma unroll
        for (int o = 0; o < OV; o++) { a1[o] = 0.0f; a2[o] = 0.0f; }
#pragma unroll
        for (int i = 0; i < DIN; i++) {
            float hi = __shfl_sync(0xffffffffu, hv[i / 32], i & 31);
            float ni = __shfl_sync(0xffffffffu, nv[i / 32], i & 31);
            float x1 = hi + ni, x2 = hi * ni;
#pragma unroll
            for (int o = 0; o < OV; o++) {
                int j = lane + 32 * o;
                if (j < DOUT) {
                    a1[o] += x1 * W1s[i * DOUT + j];
                    a2[o] += x2 * W2s[i * DOUT + j];
                }
            }
        }
#pragma unroll
        for (int o = 0; o < OV; o++) {
            int j = lane + 32 * o;
            if (j < DOUT) {
                float y1 = a1[o] + b1s[j]; y1 = (y1 > 0.0f) ? y1 : 0.01f * y1;
                float y2 = a2[o] + b2s[j]; y2 = (y2 > 0.0f) ? y2 : 0.01f * y2;
                hout[(size_t)n * DOUT + j] = y1 + y2;
            }
        }
    }
}

// ---------------- l2-normalize into output slice (warp per node) ----------------
template <int L>
__global__ __launch_bounds__(256) void k_norm(float* __restrict__ out) {
    constexpr int Dm = (L == 1) ? 64 : (L == 2) ? 32 : 16;
    constexpr int CB = (L == 1) ? 64 : (L == 2) ? 128 : 160;
    const float* hin = (L == 1) ? g_h1 : (L == 2) ? g_h2 : g_h3;
    int n = blockIdx.x * (blockDim.x >> 5) + (threadIdx.x >> 5);
    int lane = threadIdx.x & 31;
    if (n >= N_ENT) return;
    constexpr int V = (Dm + 31) / 32;
    float v[V];
    float ss = 0.0f;
#pragma unroll
    for (int k = 0; k < V; k++) {
        int c = lane + 32 * k;
        v[k] = (c < Dm) ? hin[(size_t)n * Dm + c] : 0.0f;
        ss += v[k] * v[k];
    }
#pragma unroll
    for (int o = 16; o; o >>= 1) ss += __shfl_xor_sync(0xffffffffu, ss, o);
    float nr = fmaxf(sqrtf(ss), 1e-12f);
    float inv = 1.0f / nr;
#pragma unroll
    for (int k = 0; k < V; k++) {
        int c = lane + 32 * k;
        if (c < Dm) out[(size_t)n * DOUT_TOTAL + CB + c] = v[k] * inv;
    }
}

// ---------------- copy raw ent_embed into output cols [0,64) ----------------
__global__ __launch_bounds__(256) void k_copy(const float* __restrict__ ent,
                                              float* __restrict__ out) {
    int i = blockIdx.x * blockDim.x + threadIdx.x;
    if (i < N_ENT * 64) {
        int n = i >> 6, c = i & 63;
        out[(size_t)n * DOUT_TOTAL + c] = ent[i];
    }
}

// ---------------- launch ----------------
extern "C" void kernel_launch(void* const* d_in, const int* in_sizes, int n_in,
                              void* d_out, int out_size) {
    const float* ent  = (const float*)d_in[0];
    const float* rel  = (const float*)d_in[1];
    const float* WR   = (const float*)d_in[2];
    const float* W1_0 = (const float*)d_in[3];
    const float* b1_0 = (const float*)d_in[4];
    const float* W2_0 = (const float*)d_in[5];
    const float* b2_0 = (const float*)d_in[6];
    const float* W1_1 = (const float*)d_in[7];
    const float* b1_1 = (const float*)d_in[8];
    const float* W2_1 = (const float*)d_in[9];
    const float* b2_1 = (const float*)d_in[10];
    const float* W1_2 = (const float*)d_in[11];
    const float* b1_2 = (const float*)d_in[12];
    const float* W2_2 = (const float*)d_in[13];
    const float* b2_2 = (const float*)d_in[14];
    const int* src = (const int*)d_in[15];
    const int* dst = (const int*)d_in[16];
    const int* et  = (const int*)d_in[17];
    float* out = (float*)d_out;

    const int NB_SCAN = (N_ENT + 511) / 512;   // 98

    k_zero<<<(N_ENT + 255) / 256, 256>>>();
    k_proj<<<dim3((N_ENT + 63) / 64, N_REL), 256>>>(ent, WR);
    k_att<<<(N_EDGE * 32 + 255) / 256, 256>>>(rel, src, dst, et);
    k_count<<<(N_EDGE + 255) / 256, 256>>>(dst);
    k_scan1<<<NB_SCAN, 512>>>();
    k_scan2<<<1, 32>>>(NB_SCAN);
    k_scan3<<<(N_ENT + 511) / 512, 512>>>();
    k_scatter<<<(N_EDGE + 255) / 256, 256>>>(dst);
    k_softmax<<<(N_ENT + 7) / 8, 256>>>();

    // layer 0: 64 -> 64
    k_agg<0><<<(N_ENT + 7) / 8, 256>>>(ent, src);
    k_transform<0><<<512, 256>>>(ent, W1_0, b1_0, W2_0, b2_0);
    // layer 1: 64 -> 32
    k_agg<1><<<(N_ENT + 7) / 8, 256>>>(ent, src);
    k_transform<1><<<512, 256>>>(ent, W1_1, b1_1, W2_1, b2_1);
    // layer 2: 32 -> 16
    k_agg<2><<<(N_ENT + 7) / 8, 256>>>(ent, src);
    k_transform<2><<<512, 256>>>(ent, W1_2, b1_2, W2_2, b2_2);

    // output assembly
    k_copy<<<(N_ENT * 64 + 255) / 256, 256>>>(ent, out);
    k_norm<1><<<(N_ENT + 7) / 8, 256>>>(out);
    k_norm<2><<<(N_ENT + 7) / 8, 256>>>(out);
    k_norm<3><<<(N_ENT + 7) / 8, 256>>>(out);
}

// round 3
// speedup vs baseline: 1.1813x; 1.1813x over previous
#include <cuda_runtime.h>
#include <cuda_bf16.h>
#include <math.h>

#define N_ENT  50000
#define N_REL  16
#define N_EDGE 1000000
#define DOUT_TOTAL 176

// ---------------- scratch ----------------
__device__ float g_proj[(size_t)N_REL * N_ENT * 64];   // 204.8 MB
__device__ float g_att[N_EDGE];     // attention logits, CSR(dst)-sorted order
__device__ float g_a[N_EDGE];       // softmax-normalized coefs, CSR order
__device__ int   g_deg[N_ENT];
__device__ int   g_incl[N_ENT];
__device__ int   g_offs[N_ENT + 1];
__device__ int   g_cursor[N_ENT];
__device__ int   g_bsum[256];
__device__ int   g_srcs[N_EDGE];    // src, CSR order
__device__ int   g_dsts[N_EDGE];    // dst, CSR order
__device__ int   g_ets[N_EDGE];     // etype, CSR order
__device__ float g_h1[(size_t)N_ENT * 64];
__device__ float g_h2[(size_t)N_ENT * 32];

// packed fp32x2 FMA (Blackwell dual-fp32 pipe)
__device__ __forceinline__ float2 ffma2(float2 a, float2 b, float2 c) {
    float2 d;
    asm("fma.rn.f32x2 %0, %1, %2, %3;"
        : "=l"(reinterpret_cast<unsigned long long&>(d))
        : "l"(reinterpret_cast<const unsigned long long&>(a)),
          "l"(reinterpret_cast<const unsigned long long&>(b)),
          "l"(reinterpret_cast<const unsigned long long&>(c)));
    return d;
}

// ---------------- init ----------------
__global__ __launch_bounds__(256) void k_zero() {
    int i = blockIdx.x * blockDim.x + threadIdx.x;
    if (i < N_ENT) { g_deg[i] = 0; g_cursor[i] = 0; }
}

// ---------------- proj[r,n,e] = sum_d ent[n,d] * W_R[r,d,e] ----------------
__global__ __launch_bounds__(256) void k_proj(const float* __restrict__ ent,
                                              const float* __restrict__ WR) {
    __shared__ __align__(16) float Wsm[64 * 64];
    __shared__ __align__(16) float entT[64 * 68];   // [k][node], pitch 68
    const int r  = blockIdx.y;
    const int n0 = blockIdx.x * 64;
    const int tid = threadIdx.x;

    const float* W = WR + (size_t)r * 4096;
    for (int i = tid; i < 4096; i += 256) Wsm[i] = W[i];
    for (int i = tid; i < 4096; i += 256) {
        int node = i >> 6, k = i & 63;
        int n = n0 + node;
        entT[k * 68 + node] = (n < N_ENT) ? ent[(size_t)n * 64 + k] : 0.0f;
    }
    __syncthreads();

    const int d = tid & 63;       // output column e
    const int g = tid >> 6;       // node group (16 nodes)
    float2 acc[8];
#pragma unroll
    for (int i = 0; i < 8; i++) acc[i] = make_float2(0.0f, 0.0f);

#pragma unroll 8
    for (int k = 0; k < 64; k++) {
        float w = Wsm[k * 64 + d];
        float2 w2 = make_float2(w, w);
        const float4* ep = reinterpret_cast<const float4*>(&entT[k * 68 + g * 16]);
        float4 e0 = ep[0], e1 = ep[1], e2 = ep[2], e3 = ep[3];
        acc[0] = ffma2(make_float2(e0.x, e0.y), w2, acc[0]);
        acc[1] = ffma2(make_float2(e0.z, e0.w), w2, acc[1]);
        acc[2] = ffma2(make_float2(e1.x, e1.y), w2, acc[2]);
        acc[3] = ffma2(make_float2(e1.z, e1.w), w2, acc[3]);
        acc[4] = ffma2(make_float2(e2.x, e2.y), w2, acc[4]);
        acc[5] = ffma2(make_float2(e2.z, e2.w), w2, acc[5]);
        acc[6] = ffma2(make_float2(e3.x, e3.y), w2, acc[6]);
        acc[7] = ffma2(make_float2(e3.z, e3.w), w2, acc[7]);
    }

    float* outb = g_proj + ((size_t)r * N_ENT + n0) * 64;
#pragma unroll
    for (int i = 0; i < 8; i++) {
        int node = g * 16 + 2 * i;
        if (n0 + node < N_ENT)     outb[(size_t)node * 64 + d]       = acc[i].x;
        if (n0 + node + 1 < N_ENT) outb[(size_t)(node + 1) * 64 + d] = acc[i].y;
    }
}

// ---------------- CSR build ----------------
__global__ __launch_bounds__(256) void k_count(const int* __restrict__ dst) {
    int e = blockIdx.x * blockDim.x + threadIdx.x;
    if (e < N_EDGE) atomicAdd(&g_deg[dst[e]], 1);
}

__global__ __launch_bounds__(512) void k_scan1() {
    __shared__ int sm[512];
    int i = blockIdx.x * 512 + threadIdx.x;
    int v = (i < N_ENT) ? g_deg[i] : 0;
    sm[threadIdx.x] = v;
    __syncthreads();
    for (int off = 1; off < 512; off <<= 1) {
        int t = (threadIdx.x >= off) ? sm[threadIdx.x - off] : 0;
        __syncthreads();
        sm[threadIdx.x] += t;
        __syncthreads();
    }
    if (i < N_ENT) g_incl[i] = sm[threadIdx.x];
    if (threadIdx.x == 511) g_bsum[blockIdx.x] = sm[511];
}

__global__ void k_scan2(int nb) {
    if (blockIdx.x == 0 && threadIdx.x == 0) {
        int run = 0;
        for (int b = 0; b < nb; b++) { int t = g_bsum[b]; g_bsum[b] = run; run += t; }
    }
}

__global__ __launch_bounds__(512) void k_scan3() {
    int i = blockIdx.x * blockDim.x + threadIdx.x;
    if (i < N_ENT) g_offs[i] = g_incl[i] - g_deg[i] + g_bsum[i / 512];
    if (i == 0) g_offs[N_ENT] = N_EDGE;
}

__global__ __launch_bounds__(256) void k_scatter(const int* __restrict__ src,
                                                 const int* __restrict__ dst,
                                                 const int* __restrict__ et) {
    int e = blockIdx.x * blockDim.x + threadIdx.x;
    if (e < N_EDGE) {
        int d = dst[e];
        int pos = g_offs[d] + atomicAdd(&g_cursor[d], 1);
        g_srcs[pos] = src[e];
        g_dsts[pos] = d;
        g_ets[pos]  = et[e];
    }
}

// ---------------- attention logits: warp handles 8 CSR-ordered edges ----------------
__global__ __launch_bounds__(256) void k_att(const float* __restrict__ rel) {
    int w = (blockIdx.x * blockDim.x + threadIdx.x) >> 5;
    int lane = threadIdx.x & 31;
    int base = w * 8;
    if (base >= N_EDGE) return;

    int mv = 0;
    int idx = base + (lane & 7);
    if (lane < 8)       mv = g_srcs[idx];
    else if (lane < 16) mv = g_dsts[idx];
    else if (lane < 24) mv = g_ets[idx];

    float res = 0.0f;
#pragma unroll
    for (int j = 0; j < 8; j++) {
        int s = __shfl_sync(0xffffffffu, mv, j);
        int d = __shfl_sync(0xffffffffu, mv, 8 + j);
        int r = __shfl_sync(0xffffffffu, mv, 16 + j);
        const float2* pt = reinterpret_cast<const float2*>(g_proj + ((size_t)r * N_ENT + s) * 64);
        const float2* ph = reinterpret_cast<const float2*>(g_proj + ((size_t)r * N_ENT + d) * 64);
        const float2* pr = reinterpret_cast<const float2*>(rel + (size_t)r * 64);
        float2 t = pt[lane], h = ph[lane], rr = pr[lane];
        float p = t.x * tanhf(h.x + rr.x) + t.y * tanhf(h.y + rr.y);
#pragma unroll
        for (int o = 16; o; o >>= 1) p += __shfl_xor_sync(0xffffffffu, p, o);
        if (lane == j) res = p;
    }
    if (lane < 8) g_att[base + lane] = res;   // coalesced
}

// ---------------- edge softmax by dst (warp per node, all-sequential IO) ----------------
__global__ __launch_bounds__(256) void k_softmax() {
    int n = blockIdx.x * (blockDim.x >> 5) + (threadIdx.x >> 5);
    int lane = threadIdx.x & 31;
    if (n >= N_ENT) return;
    int beg = g_offs[n], end = g_offs[n + 1];
    if (beg == end) return;
    float m = -3.4e38f;
    for (int p = beg + lane; p < end; p += 32) m = fmaxf(m, g_att[p]);
#pragma unroll
    for (int o = 16; o; o >>= 1) m = fmaxf(m, __shfl_xor_sync(0xffffffffu, m, o));
    float s = 0.0f;
    for (int p = beg + lane; p < end; p += 32) {
        float e = expf(g_att[p] - m);
        g_a[p] = e;
        s += e;
    }
#pragma unroll
    for (int o = 16; o; o >>= 1) s += __shfl_xor_sync(0xffffffffu, s, o);
    float inv = 1.0f / s;
    for (int p = beg + lane; p < end; p += 32) g_a[p] *= inv;
}

// ---------------- fused layer: agg + bi-interaction + l2norm + output ----------------
// warp per node. Wint in smem holds interleaved (W1, W2) as float2 -> FFMA2 GEMV.
template <int L>
__global__ __launch_bounds__(256) void k_layer(const float* __restrict__ ent,
                                               const float* __restrict__ W1,
                                               const float* __restrict__ b1,
                                               const float* __restrict__ W2,
                                               const float* __restrict__ b2,
                                               float* __restrict__ out) {
    constexpr int DIN  = (L == 0) ? 64 : (L == 1) ? 64 : 32;
    constexpr int DOUT = (L == 0) ? 64 : (L == 1) ? 32 : 16;
    constexpr int CB   = (L == 0) ? 64 : (L == 1) ? 128 : 160;
    constexpr int V    = DIN / 32;
    constexpr int OV   = (DOUT + 31) / 32;
    const float* hin = (L == 0) ? ent : (L == 1) ? g_h1 : g_h2;
    float* hout      = (L == 0) ? g_h1 : (L == 1) ? g_h2 : nullptr;

    __shared__ float2 Wint[DIN * DOUT];
    __shared__ float2 bint[DOUT];
    for (int i = threadIdx.x; i < DIN * DOUT; i += blockDim.x)
        Wint[i] = make_float2(W1[i], W2[i]);
    if (threadIdx.x < DOUT)
        bint[threadIdx.x] = make_float2(b1[threadIdx.x], b2[threadIdx.x]);
    __syncthreads();

    int lane = threadIdx.x & 31;
    int n = blockIdx.x * (blockDim.x >> 5) + (threadIdx.x >> 5);
    if (n >= N_ENT) return;

    // ---- aggregate Nh + own h row ----
    float hv[V], nv[V];
#pragma unroll
    for (int v = 0; v < V; v++) {
        hv[v] = hin[(size_t)n * DIN + lane + 32 * v];
        nv[v] = 0.0f;
    }
    int beg = g_offs[n], end = g_offs[n + 1];
    for (int p = beg; p < end; p++) {
        float c = g_a[p];
        const float* hs = hin + (size_t)g_srcs[p] * DIN;
#pragma unroll
        for (int v = 0; v < V; v++) nv[v] += c * hs[lane + 32 * v];
    }

    // ---- bi-interaction transform (packed: x = (h+Nh, h*Nh)) ----
    float sv1[V], sv2[V];
#pragma unroll
    for (int v = 0; v < V; v++) { sv1[v] = hv[v] + nv[v]; sv2[v] = hv[v] * nv[v]; }

    float2 acc[OV];
#pragma unroll
    for (int o = 0; o < OV; o++) acc[o] = make_float2(0.0f, 0.0f);
#pragma unroll
    for (int i = 0; i < DIN; i++) {
        float x1 = __shfl_sync(0xffffffffu, sv1[i >> 5], i & 31);
        float x2 = __shfl_sync(0xffffffffu, sv2[i >> 5], i & 31);
        float2 xp = make_float2(x1, x2);
#pragma unroll
        for (int o = 0; o < OV; o++) {
            int j = lane + 32 * o;
            if (j < DOUT) acc[o] = ffma2(xp, Wint[i * DOUT + j], acc[o]);
        }
    }

    float y[OV];
    float ss = 0.0f;
#pragma unroll
    for (int o = 0; o < OV; o++) {
        int j = lane + 32 * o;
        if (j < DOUT) {
            float y1 = acc[o].x + bint[j].x; y1 = (y1 > 0.0f) ? y1 : 0.01f * y1;
            float y2 = acc[o].y + bint[j].y; y2 = (y2 > 0.0f) ? y2 : 0.01f * y2;
            y[o] = y1 + y2;
            ss += y[o] * y[o];
        }
    }
#pragma unroll
    for (int o = 16; o; o >>= 1) ss += __shfl_xor_sync(0xffffffffu, ss, o);
    float inv = 1.0f / fmaxf(sqrtf(ss), 1e-12f);

#pragma unroll
    for (int o = 0; o < OV; o++) {
        int j = lane + 32 * o;
        if (j < DOUT) {
            if (hout) hout[(size_t)n * DOUT + j] = y[o];
            out[(size_t)n * DOUT_TOTAL + CB + j] = y[o] * inv;
        }
    }
    if (L == 0) {   // fused copy of raw ent row into out cols [0,64)
#pragma unroll
        for (int v = 0; v < V; v++)
            out[(size_t)n * DOUT_TOTAL + lane + 32 * v] = hv[v];
    }
}

// ---------------- launch ----------------
extern "C" void kernel_launch(void* const* d_in, const int* in_sizes, int n_in,
                              void* d_out, int out_size) {
    const float* ent  = (const float*)d_in[0];
    const float* rel  = (const float*)d_in[1];
    const float* WR   = (const float*)d_in[2];
    const float* W1_0 = (const float*)d_in[3];
    const float* b1_0 = (const float*)d_in[4];
    const float* W2_0 = (const float*)d_in[5];
    const float* b2_0 = (const float*)d_in[6];
    const float* W1_1 = (const float*)d_in[7];
    const float* b1_1 = (const float*)d_in[8];
    const float* W2_1 = (const float*)d_in[9];
    const float* b2_1 = (const float*)d_in[10];
    const float* W1_2 = (const float*)d_in[11];
    const float* b1_2 = (const float*)d_in[12];
    const float* W2_2 = (const float*)d_in[13];
    const float* b2_2 = (const float*)d_in[14];
    const int* src = (const int*)d_in[15];
    const int* dst = (const int*)d_in[16];
    const int* et  = (const int*)d_in[17];
    float* out = (float*)d_out;

    const int NB_SCAN = (N_ENT + 511) / 512;   // 98

    k_zero<<<(N_ENT + 255) / 256, 256>>>();
    k_count<<<(N_EDGE + 255) / 256, 256>>>(dst);
    k_scan1<<<NB_SCAN, 512>>>();
    k_proj<<<dim3((N_ENT + 63) / 64, N_REL), 256>>>(ent, WR);
    k_scan2<<<1, 32>>>(NB_SCAN);
    k_scan3<<<(N_ENT + 511) / 512, 512>>>();
    k_scatter<<<(N_EDGE + 255) / 256, 256>>>(src, dst, et);
    k_att<<<(N_EDGE / 8 + 7) / 8, 256>>>(rel);
    k_softmax<<<(N_ENT + 7) / 8, 256>>>();
    k_layer<0><<<(N_ENT + 7) / 8, 256>>>(ent, W1_0, b1_0, W2_0, b2_0, out);
    k_layer<1><<<(N_ENT + 7) / 8, 256>>>(ent, W1_1, b1_1, W2_1, b2_1, out);
    k_layer<2><<<(N_ENT + 7) / 8, 256>>>(ent, W1_2, b1_2, W2_2, b2_2, out);
}

// round 4
// speedup vs baseline: 1.1892x; 1.0067x over previous
#include <cuda_runtime.h>
#include <cuda_bf16.h>
#include <math.h>

#define N_ENT  50000
#define N_REL  16
#define N_EDGE 1000000
#define DOUT_TOTAL 176

// ---------------- scratch ----------------
__device__ float g_proj[(size_t)N_REL * N_ENT * 64];   // 204.8 MB
__device__ float g_att[N_EDGE];     // attention logits, CSR(dst)-sorted order
__device__ float g_a[N_EDGE];       // softmax-normalized coefs, CSR order
__device__ int   g_deg[N_ENT];
__device__ int   g_incl[N_ENT];
__device__ int   g_offs[N_ENT + 1];
__device__ int   g_cursor[N_ENT];
__device__ int   g_bsum[256];
__device__ int   g_srcs[N_EDGE];    // src, CSR order
__device__ int   g_dsts[N_EDGE];    // dst, CSR order
__device__ int   g_ets[N_EDGE];     // etype, CSR order
__device__ float g_h1[(size_t)N_ENT * 64];
__device__ float g_h2[(size_t)N_ENT * 32];

// packed fp32x2 FMA (Blackwell dual-fp32 pipe)
__device__ __forceinline__ float2 ffma2(float2 a, float2 b, float2 c) {
    float2 d;
    asm("fma.rn.f32x2 %0, %1, %2, %3;"
        : "=l"(reinterpret_cast<unsigned long long&>(d))
        : "l"(reinterpret_cast<const unsigned long long&>(a)),
          "l"(reinterpret_cast<const unsigned long long&>(b)),
          "l"(reinterpret_cast<const unsigned long long&>(c)));
    return d;
}

// ---------------- init ----------------
__global__ __launch_bounds__(256) void k_zero() {
    int i = blockIdx.x * blockDim.x + threadIdx.x;
    if (i < N_ENT) { g_deg[i] = 0; g_cursor[i] = 0; }
}

// ---------------- proj[r,n,e] = sum_d ent[n,d] * W_R[r,d,e] ----------------
__global__ __launch_bounds__(256) void k_proj(const float* __restrict__ ent,
                                              const float* __restrict__ WR) {
    __shared__ __align__(16) float Wsm[64 * 64];
    __shared__ __align__(16) float entT[64 * 68];   // [k][node], pitch 68
    const int r  = blockIdx.y;
    const int n0 = blockIdx.x * 64;
    const int tid = threadIdx.x;

    const float* W = WR + (size_t)r * 4096;
    for (int i = tid; i < 4096; i += 256) Wsm[i] = W[i];
    for (int i = tid; i < 4096; i += 256) {
        int node = i >> 6, k = i & 63;
        int n = n0 + node;
        entT[k * 68 + node] = (n < N_ENT) ? ent[(size_t)n * 64 + k] : 0.0f;
    }
    __syncthreads();

    const int d = tid & 63;       // output column e
    const int g = tid >> 6;       // node group (16 nodes)
    float2 acc[8];
#pragma unroll
    for (int i = 0; i < 8; i++) acc[i] = make_float2(0.0f, 0.0f);

#pragma unroll 8
    for (int k = 0; k < 64; k++) {
        float w = Wsm[k * 64 + d];
        float2 w2 = make_float2(w, w);
        const float4* ep = reinterpret_cast<const float4*>(&entT[k * 68 + g * 16]);
        float4 e0 = ep[0], e1 = ep[1], e2 = ep[2], e3 = ep[3];
        acc[0] = ffma2(make_float2(e0.x, e0.y), w2, acc[0]);
        acc[1] = ffma2(make_float2(e0.z, e0.w), w2, acc[1]);
        acc[2] = ffma2(make_float2(e1.x, e1.y), w2, acc[2]);
        acc[3] = ffma2(make_float2(e1.z, e1.w), w2, acc[3]);
        acc[4] = ffma2(make_float2(e2.x, e2.y), w2, acc[4]);
        acc[5] = ffma2(make_float2(e2.z, e2.w), w2, acc[5]);
        acc[6] = ffma2(make_float2(e3.x, e3.y), w2, acc[6]);
        acc[7] = ffma2(make_float2(e3.z, e3.w), w2, acc[7]);
    }

    float* outb = g_proj + ((size_t)r * N_ENT + n0) * 64;
#pragma unroll
    for (int i = 0; i < 8; i++) {
        int node = g * 16 + 2 * i;
        if (n0 + node < N_ENT)     outb[(size_t)node * 64 + d]       = acc[i].x;
        if (n0 + node + 1 < N_ENT) outb[(size_t)(node + 1) * 64 + d] = acc[i].y;
    }
}

// ---------------- CSR build ----------------
__global__ __launch_bounds__(256) void k_count(const int* __restrict__ dst) {
    int e = blockIdx.x * blockDim.x + threadIdx.x;
    if (e < N_EDGE) atomicAdd(&g_deg[dst[e]], 1);
}

__global__ __launch_bounds__(512) void k_scan1() {
    __shared__ int sm[512];
    int i = blockIdx.x * 512 + threadIdx.x;
    int v = (i < N_ENT) ? g_deg[i] : 0;
    sm[threadIdx.x] = v;
    __syncthreads();
    for (int off = 1; off < 512; off <<= 1) {
        int t = (threadIdx.x >= off) ? sm[threadIdx.x - off] : 0;
        __syncthreads();
        sm[threadIdx.x] += t;
        __syncthreads();
    }
    if (i < N_ENT) g_incl[i] = sm[threadIdx.x];
    if (threadIdx.x == 511) g_bsum[blockIdx.x] = sm[511];
}

__global__ void k_scan2(int nb) {
    if (blockIdx.x == 0 && threadIdx.x == 0) {
        int run = 0;
        for (int b = 0; b < nb; b++) { int t = g_bsum[b]; g_bsum[b] = run; run += t; }
    }
}

__global__ __launch_bounds__(512) void k_scan3() {
    int i = blockIdx.x * blockDim.x + threadIdx.x;
    if (i < N_ENT) g_offs[i] = g_incl[i] - g_deg[i] + g_bsum[i / 512];
    if (i == 0) g_offs[N_ENT] = N_EDGE;
}

__global__ __launch_bounds__(256) void k_scatter(const int* __restrict__ src,
                                                 const int* __restrict__ dst,
                                                 const int* __restrict__ et) {
    int e = blockIdx.x * blockDim.x + threadIdx.x;
    if (e < N_EDGE) {
        int d = dst[e];
        int pos = g_offs[d] + atomicAdd(&g_cursor[d], 1);
        g_srcs[pos] = src[e];
        g_dsts[pos] = d;
        g_ets[pos]  = et[e];
    }
}

// ---------------- attention logits: warp handles 8 CSR-ordered edges ----------------
__global__ __launch_bounds__(256) void k_att(const float* __restrict__ rel) {
    int w = (blockIdx.x * blockDim.x + threadIdx.x) >> 5;
    int lane = threadIdx.x & 31;
    int base = w * 8;
    if (base >= N_EDGE) return;

    int mv = 0;
    int idx = base + (lane & 7);
    if (lane < 8)       mv = g_srcs[idx];
    else if (lane < 16) mv = g_dsts[idx];
    else if (lane < 24) mv = g_ets[idx];

    float res = 0.0f;
#pragma unroll
    for (int j = 0; j < 8; j++) {
        int s = __shfl_sync(0xffffffffu, mv, j);
        int d = __shfl_sync(0xffffffffu, mv, 8 + j);
        int r = __shfl_sync(0xffffffffu, mv, 16 + j);
        const float2* pt = reinterpret_cast<const float2*>(g_proj + ((size_t)r * N_ENT + s) * 64);
        const float2* ph = reinterpret_cast<const float2*>(g_proj + ((size_t)r * N_ENT + d) * 64);
        const float2* pr = reinterpret_cast<const float2*>(rel + (size_t)r * 64);
        float2 t = pt[lane], h = ph[lane], rr = pr[lane];
        float p = t.x * tanhf(h.x + rr.x) + t.y * tanhf(h.y + rr.y);
#pragma unroll
        for (int o = 16; o; o >>= 1) p += __shfl_xor_sync(0xffffffffu, p, o);
        if (lane == j) res = p;
    }
    if (lane < 8) g_att[base + lane] = res;   // coalesced
}

// ---------------- edge softmax by dst (warp per node, all-sequential IO) ----------------
__global__ __launch_bounds__(256) void k_softmax() {
    int n = blockIdx.x * (blockDim.x >> 5) + (threadIdx.x >> 5);
    int lane = threadIdx.x & 31;
    if (n >= N_ENT) return;
    int beg = g_offs[n], end = g_offs[n + 1];
    if (beg == end) return;
    float m = -3.4e38f;
    for (int p = beg + lane; p < end; p += 32) m = fmaxf(m, g_att[p]);
#pragma unroll
    for (int o = 16; o; o >>= 1) m = fmaxf(m, __shfl_xor_sync(0xffffffffu, m, o));
    float s = 0.0f;
    for (int p = beg + lane; p < end; p += 32) {
        float e = expf(g_att[p] - m);
        g_a[p] = e;
        s += e;
    }
#pragma unroll
    for (int o = 16; o; o >>= 1) s += __shfl_xor_sync(0xffffffffu, s, o);
    float inv = 1.0f / s;
    for (int p = beg + lane; p < end; p += 32) g_a[p] *= inv;
}

// ---------------- fused layer: agg + bi-interaction + l2norm + output ----------------
// warp per node. Wint in smem holds interleaved (W1, W2) as float2 -> FFMA2 GEMV.
template <int L>
__global__ __launch_bounds__(256) void k_layer(const float* __restrict__ ent,
                                               const float* __restrict__ W1,
                                               const float* __restrict__ b1,
                                               const float* __restrict__ W2,
                                               const float* __restrict__ b2,
                                               float* __restrict__ out) {
    constexpr int DIN  = (L == 0) ? 64 : (L == 1) ? 64 : 32;
    constexpr int DOUT = (L == 0) ? 64 : (L == 1) ? 32 : 16;
    constexpr int CB   = (L == 0) ? 64 : (L == 1) ? 128 : 160;
    constexpr int V    = DIN / 32;
    constexpr int OV   = (DOUT + 31) / 32;
    const float* hin = (L == 0) ? ent : (L == 1) ? g_h1 : g_h2;
    float* hout      = (L == 0) ? g_h1 : (L == 1) ? g_h2 : nullptr;

    __shared__ float2 Wint[DIN * DOUT];
    __shared__ float2 bint[DOUT];
    for (int i = threadIdx.x; i < DIN * DOUT; i += blockDim.x)
        Wint[i] = make_float2(W1[i], W2[i]);
    if (threadIdx.x < DOUT)
        bint[threadIdx.x] = make_float2(b1[threadIdx.x], b2[threadIdx.x]);
    __syncthreads();

    int lane = threadIdx.x & 31;
    int n = blockIdx.x * (blockDim.x >> 5) + (threadIdx.x >> 5);
    if (n >= N_ENT) return;

    // ---- aggregate Nh + own h row ----
    float hv[V], nv[V];
#pragma unroll
    for (int v = 0; v < V; v++) {
        hv[v] = hin[(size_t)n * DIN + lane + 32 * v];
        nv[v] = 0.0f;
    }
    int beg = g_offs[n], end = g_offs[n + 1];
    for (int p = beg; p < end; p++) {
        float c = g_a[p];
        const float* hs = hin + (size_t)g_srcs[p] * DIN;
#pragma unroll
        for (int v = 0; v < V; v++) nv[v] += c * hs[lane + 32 * v];
    }

    // ---- bi-interaction transform (packed: x = (h+Nh, h*Nh)) ----
    float sv1[V], sv2[V];
#pragma unroll
    for (int v = 0; v < V; v++) { sv1[v] = hv[v] + nv[v]; sv2[v] = hv[v] * nv[v]; }

    float2 acc[OV];
#pragma unroll
    for (int o = 0; o < OV; o++) acc[o] = make_float2(0.0f, 0.0f);
#pragma unroll
    for (int i = 0; i < DIN; i++) {
        float x1 = __shfl_sync(0xffffffffu, sv1[i >> 5], i & 31);
        float x2 = __shfl_sync(0xffffffffu, sv2[i >> 5], i & 31);
        float2 xp = make_float2(x1, x2);
#pragma unroll
        for (int o = 0; o < OV; o++) {
            int j = lane + 32 * o;
            if (j < DOUT) acc[o] = ffma2(xp, Wint[i * DOUT + j], acc[o]);
        }
    }

    float y[OV];
    float ss = 0.0f;
#pragma unroll
    for (int o = 0; o < OV; o++) {
        int j = lane + 32 * o;
        if (j < DOUT) {
            float y1 = acc[o].x + bint[j].x; y1 = (y1 > 0.0f) ? y1 : 0.01f * y1;
            float y2 = acc[o].y + bint[j].y; y2 = (y2 > 0.0f) ? y2 : 0.01f * y2;
            y[o] = y1 + y2;
            ss += y[o] * y[o];
        }
    }
#pragma unroll
    for (int o = 16; o; o >>= 1) ss += __shfl_xor_sync(0xffffffffu, ss, o);
    float inv = 1.0f / fmaxf(sqrtf(ss), 1e-12f);

#pragma unroll
    for (int o = 0; o < OV; o++) {
        int j = lane + 32 * o;
        if (j < DOUT) {
            if (hout) hout[(size_t)n * DOUT + j] = y[o];
            out[(size_t)n * DOUT_TOTAL + CB + j] = y[o] * inv;
        }
    }
    if (L == 0) {   // fused copy of raw ent row into out cols [0,64)
#pragma unroll
        for (int v = 0; v < V; v++)
            out[(size_t)n * DOUT_TOTAL + lane + 32 * v] = hv[v];
    }
}

// ---------------- launch ----------------
extern "C" void kernel_launch(void* const* d_in, const int* in_sizes, int n_in,
                              void* d_out, int out_size) {
    const float* ent  = (const float*)d_in[0];
    const float* rel  = (const float*)d_in[1];
    const float* WR   = (const float*)d_in[2];
    const float* W1_0 = (const float*)d_in[3];
    const float* b1_0 = (const float*)d_in[4];
    const float* W2_0 = (const float*)d_in[5];
    const float* b2_0 = (const float*)d_in[6];
    const float* W1_1 = (const float*)d_in[7];
    const float* b1_1 = (const float*)d_in[8];
    const float* W2_1 = (const float*)d_in[9];
    const float* b2_1 = (const float*)d_in[10];
    const float* W1_2 = (const float*)d_in[11];
    const float* b1_2 = (const float*)d_in[12];
    const float* W2_2 = (const float*)d_in[13];
    const float* b2_2 = (const float*)d_in[14];
    const int* src = (const int*)d_in[15];
    const int* dst = (const int*)d_in[16];
    const int* et  = (const int*)d_in[17];
    float* out = (float*)d_out;

    const int NB_SCAN = (N_ENT + 511) / 512;   // 98

    k_zero<<<(N_ENT + 255) / 256, 256>>>();
    k_count<<<(N_EDGE + 255) / 256, 256>>>(dst);
    k_scan1<<<NB_SCAN, 512>>>();
    k_proj<<<dim3((N_ENT + 63) / 64, N_REL), 256>>>(ent, WR);
    k_scan2<<<1, 32>>>(NB_SCAN);
    k_scan3<<<(N_ENT + 511) / 512, 512>>>();
    k_scatter<<<(N_EDGE + 255) / 256, 256>>>(src, dst, et);
    k_att<<<(N_EDGE / 8 + 7) / 8, 256>>>(rel);
    k_softmax<<<(N_ENT + 7) / 8, 256>>>();
    k_layer<0><<<(N_ENT + 7) / 8, 256>>>(ent, W1_0, b1_0, W2_0, b2_0, out);
    k_layer<1><<<(N_ENT + 7) / 8, 256>>>(ent, W1_1, b1_1, W2_1, b2_1, out);
    k_layer<2><<<(N_ENT + 7) / 8, 256>>>(ent, W1_2, b1_2, W2_2, b2_2, out);
}

// round 5
// speedup vs baseline: 1.4382x; 1.2094x over previous
#include <cuda_runtime.h>
#include <cuda_bf16.h>
#include <math.h>

#define N_ENT  50000
#define N_REL  16
#define N_EDGE 1000000
#define DOUT_TOTAL 176

// ---------------- scratch ----------------
__device__ float g_proj[(size_t)N_REL * N_ENT * 64];   // 204.8 MB
__device__ float g_att[N_EDGE];     // attention logits, CSR(dst)-sorted order
__device__ float g_a[N_EDGE];       // softmax-normalized coefs, CSR order
__device__ int   g_deg[N_ENT];
__device__ int   g_incl[N_ENT];
__device__ int   g_offs[N_ENT + 1];
__device__ int   g_cursor[N_ENT];
__device__ int   g_bsum[256];
__device__ int   g_srcs[N_EDGE];    // src, CSR order
__device__ int   g_dsts[N_EDGE];    // dst, CSR order
__device__ int   g_ets[N_EDGE];     // etype, CSR order
__device__ float g_h1[(size_t)N_ENT * 64];
__device__ float g_h2[(size_t)N_ENT * 32];

// packed fp32x2 FMA (Blackwell dual-fp32 pipe)
__device__ __forceinline__ float2 ffma2(float2 a, float2 b, float2 c) {
    float2 d;
    asm("fma.rn.f32x2 %0, %1, %2, %3;"
        : "=l"(reinterpret_cast<unsigned long long&>(d))
        : "l"(reinterpret_cast<const unsigned long long&>(a)),
          "l"(reinterpret_cast<const unsigned long long&>(b)),
          "l"(reinterpret_cast<const unsigned long long&>(c)));
    return d;
}

// ---------------- init ----------------
__global__ __launch_bounds__(256) void k_zero() {
    int i = blockIdx.x * blockDim.x + threadIdx.x;
    if (i < N_ENT) { g_deg[i] = 0; g_cursor[i] = 0; }
}

// ---------------- proj[r,n,e] = sum_d ent[n,d] * W_R[r,d,e] ----------------
// Block: 128 threads, tile = 128 nodes x 64 cols, 4 relations per block.
// Thread tile: 8 nodes (4 float2 pairs) x 8 strided cols -> 1.0 B SMEM / MAC.
#define PROJ_NODES 128
__global__ __launch_bounds__(128) void k_proj(const float* __restrict__ ent,
                                              const float* __restrict__ WR) {
    __shared__ __align__(16) float entT[64 * PROJ_NODES];  // [k][node] 32KB
    __shared__ __align__(16) float Wsm[64 * 64];           // 16KB
    const int tid = threadIdx.x;
    const int n0  = blockIdx.x * PROJ_NODES;

    // fill entT: thread owns node `tid` -> conflict-free STS (bank = tid%32)
    {
        int n = n0 + tid;
        if (n < N_ENT) {
            const float4* er = reinterpret_cast<const float4*>(ent + (size_t)n * 64);
#pragma unroll
            for (int q = 0; q < 16; q++) {
                float4 v = er[q];
                entT[(4 * q + 0) * PROJ_NODES + tid] = v.x;
                entT[(4 * q + 1) * PROJ_NODES + tid] = v.y;
                entT[(4 * q + 2) * PROJ_NODES + tid] = v.z;
                entT[(4 * q + 3) * PROJ_NODES + tid] = v.w;
            }
        } else {
#pragma unroll
            for (int q = 0; q < 16; q++) {
                entT[(4 * q + 0) * PROJ_NODES + tid] = 0.0f;
                entT[(4 * q + 1) * PROJ_NODES + tid] = 0.0f;
                entT[(4 * q + 2) * PROJ_NODES + tid] = 0.0f;
                entT[(4 * q + 3) * PROJ_NODES + tid] = 0.0f;
            }
        }
    }

    const int cb = tid & 7;    // col group: cols cb + 8j
    const int nb = tid >> 3;   // node group: nodes nb*8 .. +7

    for (int rr = 0; rr < 4; rr++) {
        const int r = blockIdx.y * 4 + rr;
        __syncthreads();   // entT ready / previous relation's Wsm reads done
        const float* W = WR + (size_t)r * 4096;
        for (int i = tid; i < 4096; i += 128) Wsm[i] = W[i];
        __syncthreads();

        float2 acc[4][8];
#pragma unroll
        for (int p = 0; p < 4; p++)
#pragma unroll
            for (int j = 0; j < 8; j++) acc[p][j] = make_float2(0.0f, 0.0f);

#pragma unroll 4
        for (int k = 0; k < 64; k++) {
            const float4* eb = reinterpret_cast<const float4*>(&entT[k * PROJ_NODES + nb * 8]);
            float4 ea = eb[0], eb1 = eb[1];
            float2 ep[4];
            ep[0] = make_float2(ea.x, ea.y);
            ep[1] = make_float2(ea.z, ea.w);
            ep[2] = make_float2(eb1.x, eb1.y);
            ep[3] = make_float2(eb1.z, eb1.w);
#pragma unroll
            for (int j = 0; j < 8; j++) {
                float w = Wsm[k * 64 + cb + 8 * j];
                float2 w2 = make_float2(w, w);
#pragma unroll
                for (int p = 0; p < 4; p++) acc[p][j] = ffma2(ep[p], w2, acc[p][j]);
            }
        }

        float* outb = g_proj + ((size_t)r * N_ENT + n0) * 64;
#pragma unroll
        for (int p = 0; p < 4; p++) {
            int node = nb * 8 + 2 * p;
            bool ok0 = (n0 + node) < N_ENT;
            bool ok1 = (n0 + node + 1) < N_ENT;
#pragma unroll
            for (int j = 0; j < 8; j++) {
                int col = cb + 8 * j;
                if (ok0) outb[(size_t)node * 64 + col] = acc[p][j].x;
                if (ok1) outb[(size_t)(node + 1) * 64 + col] = acc[p][j].y;
            }
        }
    }
}

// ---------------- CSR build ----------------
__global__ __launch_bounds__(256) void k_count(const int* __restrict__ dst) {
    int e = blockIdx.x * blockDim.x + threadIdx.x;
    if (e < N_EDGE) atomicAdd(&g_deg[dst[e]], 1);
}

__global__ __launch_bounds__(512) void k_scan1() {
    __shared__ int sm[512];
    int i = blockIdx.x * 512 + threadIdx.x;
    int v = (i < N_ENT) ? g_deg[i] : 0;
    sm[threadIdx.x] = v;
    __syncthreads();
    for (int off = 1; off < 512; off <<= 1) {
        int t = (threadIdx.x >= off) ? sm[threadIdx.x - off] : 0;
        __syncthreads();
        sm[threadIdx.x] += t;
        __syncthreads();
    }
    if (i < N_ENT) g_incl[i] = sm[threadIdx.x];
    if (threadIdx.x == 511) g_bsum[blockIdx.x] = sm[511];
}

__global__ void k_scan2(int nb) {
    if (blockIdx.x == 0 && threadIdx.x == 0) {
        int run = 0;
        for (int b = 0; b < nb; b++) { int t = g_bsum[b]; g_bsum[b] = run; run += t; }
    }
}

__global__ __launch_bounds__(512) void k_scan3() {
    int i = blockIdx.x * blockDim.x + threadIdx.x;
    if (i < N_ENT) g_offs[i] = g_incl[i] - g_deg[i] + g_bsum[i / 512];
    if (i == 0) g_offs[N_ENT] = N_EDGE;
}

__global__ __launch_bounds__(256) void k_scatter(const int* __restrict__ src,
                                                 const int* __restrict__ dst,
                                                 const int* __restrict__ et) {
    int e = blockIdx.x * blockDim.x + threadIdx.x;
    if (e < N_EDGE) {
        int d = dst[e];
        int pos = g_offs[d] + atomicAdd(&g_cursor[d], 1);
        g_srcs[pos] = src[e];
        g_dsts[pos] = d;
        g_ets[pos]  = et[e];
    }
}

// ---------------- attention logits: warp handles 8 CSR-ordered edges ----------------
__global__ __launch_bounds__(256) void k_att(const float* __restrict__ rel) {
    int w = (blockIdx.x * blockDim.x + threadIdx.x) >> 5;
    int lane = threadIdx.x & 31;
    int base = w * 8;
    if (base >= N_EDGE) return;

    int mv = 0;
    int idx = base + (lane & 7);
    if (lane < 8)       mv = g_srcs[idx];
    else if (lane < 16) mv = g_dsts[idx];
    else if (lane < 24) mv = g_ets[idx];

    float res = 0.0f;
#pragma unroll
    for (int j = 0; j < 8; j++) {
        int s = __shfl_sync(0xffffffffu, mv, j);
        int d = __shfl_sync(0xffffffffu, mv, 8 + j);
        int r = __shfl_sync(0xffffffffu, mv, 16 + j);
        const float2* pt = reinterpret_cast<const float2*>(g_proj + ((size_t)r * N_ENT + s) * 64);
        const float2* ph = reinterpret_cast<const float2*>(g_proj + ((size_t)r * N_ENT + d) * 64);
        const float2* pr = reinterpret_cast<const float2*>(rel + (size_t)r * 64);
        float2 t = pt[lane], h = ph[lane], rr = pr[lane];
        float p = t.x * tanhf(h.x + rr.x) + t.y * tanhf(h.y + rr.y);
#pragma unroll
        for (int o = 16; o; o >>= 1) p += __shfl_xor_sync(0xffffffffu, p, o);
        if (lane == j) res = p;
    }
    if (lane < 8) g_att[base + lane] = res;   // coalesced
}

// ---------------- edge softmax by dst (warp per node, all-sequential IO) ----------------
__global__ __launch_bounds__(256) void k_softmax() {
    int n = blockIdx.x * (blockDim.x >> 5) + (threadIdx.x >> 5);
    int lane = threadIdx.x & 31;
    if (n >= N_ENT) return;
    int beg = g_offs[n], end = g_offs[n + 1];
    if (beg == end) return;
    float m = -3.4e38f;
    for (int p = beg + lane; p < end; p += 32) m = fmaxf(m, g_att[p]);
#pragma unroll
    for (int o = 16; o; o >>= 1) m = fmaxf(m, __shfl_xor_sync(0xffffffffu, m, o));
    float s = 0.0f;
    for (int p = beg + lane; p < end; p += 32) {
        float e = expf(g_att[p] - m);
        g_a[p] = e;
        s += e;
    }
#pragma unroll
    for (int o = 16; o; o >>= 1) s += __shfl_xor_sync(0xffffffffu, s, o);
    float inv = 1.0f / s;
    for (int p = beg + lane; p < end; p += 32) g_a[p] *= inv;
}

// ---------------- fused layer: agg + bi-interaction + l2norm + output ----------------
template <int L>
__global__ __launch_bounds__(256) void k_layer(const float* __restrict__ ent,
                                               const float* __restrict__ W1,
                                               const float* __restrict__ b1,
                                               const float* __restrict__ W2,
                                               const float* __restrict__ b2,
                                               float* __restrict__ out) {
    constexpr int DIN  = (L == 0) ? 64 : (L == 1) ? 64 : 32;
    constexpr int DOUT = (L == 0) ? 64 : (L == 1) ? 32 : 16;
    constexpr int CB   = (L == 0) ? 64 : (L == 1) ? 128 : 160;
    constexpr int V    = DIN / 32;
    constexpr int OV   = (DOUT + 31) / 32;
    const float* hin = (L == 0) ? ent : (L == 1) ? g_h1 : g_h2;
    float* hout      = (L == 0) ? g_h1 : (L == 1) ? g_h2 : nullptr;

    __shared__ float2 Wint[DIN * DOUT];
    __shared__ float2 bint[DOUT];
    for (int i = threadIdx.x; i < DIN * DOUT; i += blockDim.x)
        Wint[i] = make_float2(W1[i], W2[i]);
    if (threadIdx.x < DOUT)
        bint[threadIdx.x] = make_float2(b1[threadIdx.x], b2[threadIdx.x]);
    __syncthreads();

    int lane = threadIdx.x & 31;
    int n = blockIdx.x * (blockDim.x >> 5) + (threadIdx.x >> 5);
    if (n >= N_ENT) return;

    float hv[V], nv[V];
#pragma unroll
    for (int v = 0; v < V; v++) {
        hv[v] = hin[(size_t)n * DIN + lane + 32 * v];
        nv[v] = 0.0f;
    }
    int beg = g_offs[n], end = g_offs[n + 1];
    for (int p = beg; p < end; p++) {
        float c = g_a[p];
        const float* hs = hin + (size_t)g_srcs[p] * DIN;
#pragma unroll
        for (int v = 0; v < V; v++) nv[v] += c * hs[lane + 32 * v];
    }

    float sv1[V], sv2[V];
#pragma unroll
    for (int v = 0; v < V; v++) { sv1[v] = hv[v] + nv[v]; sv2[v] = hv[v] * nv[v]; }

    float2 acc[OV];
#pragma unroll
    for (int o = 0; o < OV; o++) acc[o] = make_float2(0.0f, 0.0f);
#pragma unroll
    for (int i = 0; i < DIN; i++) {
        float x1 = __shfl_sync(0xffffffffu, sv1[i >> 5], i & 31);
        float x2 = __shfl_sync(0xffffffffu, sv2[i >> 5], i & 31);
        float2 xp = make_float2(x1, x2);
#pragma unroll
        for (int o = 0; o < OV; o++) {
            int j = lane + 32 * o;
            if (j < DOUT) acc[o] = ffma2(xp, Wint[i * DOUT + j], acc[o]);
        }
    }

    float y[OV];
    float ss = 0.0f;
#pragma unroll
    for (int o = 0; o < OV; o++) {
        int j = lane + 32 * o;
        if (j < DOUT) {
            float y1 = acc[o].x + bint[j].x; y1 = (y1 > 0.0f) ? y1 : 0.01f * y1;
            float y2 = acc[o].y + bint[j].y; y2 = (y2 > 0.0f) ? y2 : 0.01f * y2;
            y[o] = y1 + y2;
            ss += y[o] * y[o];
        }
    }
#pragma unroll
    for (int o = 16; o; o >>= 1) ss += __shfl_xor_sync(0xffffffffu, ss, o);
    float inv = 1.0f / fmaxf(sqrtf(ss), 1e-12f);

#pragma unroll
    for (int o = 0; o < OV; o++) {
        int j = lane + 32 * o;
        if (j < DOUT) {
            if (hout) hout[(size_t)n * DOUT + j] = y[o];
            out[(size_t)n * DOUT_TOTAL + CB + j] = y[o] * inv;
        }
    }
    if (L == 0) {
#pragma unroll
        for (int v = 0; v < V; v++)
            out[(size_t)n * DOUT_TOTAL + lane + 32 * v] = hv[v];
    }
}

// ---------------- launch ----------------
extern "C" void kernel_launch(void* const* d_in, const int* in_sizes, int n_in,
                              void* d_out, int out_size) {
    const float* ent  = (const float*)d_in[0];
    const float* rel  = (const float*)d_in[1];
    const float* WR   = (const float*)d_in[2];
    const float* W1_0 = (const float*)d_in[3];
    const float* b1_0 = (const float*)d_in[4];
    const float* W2_0 = (const float*)d_in[5];
    const float* b2_0 = (const float*)d_in[6];
    const float* W1_1 = (const float*)d_in[7];
    const float* b1_1 = (const float*)d_in[8];
    const float* W2_1 = (const float*)d_in[9];
    const float* b2_1 = (const float*)d_in[10];
    const float* W1_2 = (const float*)d_in[11];
    const float* b1_2 = (const float*)d_in[12];
    const float* W2_2 = (const float*)d_in[13];
    const float* b2_2 = (const float*)d_in[14];
    const int* src = (const int*)d_in[15];
    const int* dst = (const int*)d_in[16];
    const int* et  = (const int*)d_in[17];
    float* out = (float*)d_out;

    const int NB_SCAN = (N_ENT + 511) / 512;   // 98

    k_zero<<<(N_ENT + 255) / 256, 256>>>();
    k_count<<<(N_EDGE + 255) / 256, 256>>>(dst);
    k_scan1<<<NB_SCAN, 512>>>();
    k_proj<<<dim3((N_ENT + PROJ_NODES - 1) / PROJ_NODES, N_REL / 4), 128>>>(ent, WR);
    k_scan2<<<1, 32>>>(NB_SCAN);
    k_scan3<<<(N_ENT + 511) / 512, 512>>>();
    k_scatter<<<(N_EDGE + 255) / 256, 256>>>(src, dst, et);
    k_att<<<(N_EDGE / 8 + 7) / 8, 256>>>(rel);
    k_softmax<<<(N_ENT + 7) / 8, 256>>>();
    k_layer<0><<<(N_ENT + 7) / 8, 256>>>(ent, W1_0, b1_0, W2_0, b2_0, out);
    k_layer<1><<<(N_ENT + 7) / 8, 256>>>(ent, W1_1, b1_1, W2_1, b2_1, out);
    k_layer<2><<<(N_ENT + 7) / 8, 256>>>(ent, W1_2, b1_2, W2_2, b2_2, out);
}

// round 6
// speedup vs baseline: 1.4430x; 1.0033x over previous
#include <cuda_runtime.h>
#include <cuda_bf16.h>
#include <math.h>

#define N_ENT  50000
#define N_REL  16
#define N_EDGE 1000000
#define DOUT_TOTAL 176

// ---------------- scratch ----------------
__device__ float g_proj[(size_t)N_REL * N_ENT * 64];   // 204.8 MB
__device__ float g_att[N_EDGE];     // attention logits, CSR(dst)-sorted order
__device__ float g_a[N_EDGE];       // softmax-normalized coefs, CSR order
__device__ int   g_deg[N_ENT];
__device__ int   g_incl[N_ENT];
__device__ int   g_offs[N_ENT + 1];
__device__ int   g_cursor[N_ENT];
__device__ int   g_bsum[256];
__device__ int   g_srcs[N_EDGE];    // src, CSR order
__device__ int   g_dsts[N_EDGE];    // dst, CSR order
__device__ int   g_ets[N_EDGE];     // etype, CSR order
__device__ float g_h1[(size_t)N_ENT * 64];
__device__ float g_h2[(size_t)N_ENT * 32];

// packed fp32x2 FMA (Blackwell dual-fp32 pipe)
__device__ __forceinline__ float2 ffma2(float2 a, float2 b, float2 c) {
    float2 d;
    asm("fma.rn.f32x2 %0, %1, %2, %3;"
        : "=l"(reinterpret_cast<unsigned long long&>(d))
        : "l"(reinterpret_cast<const unsigned long long&>(a)),
          "l"(reinterpret_cast<const unsigned long long&>(b)),
          "l"(reinterpret_cast<const unsigned long long&>(c)));
    return d;
}

// ---------------- init ----------------
__global__ __launch_bounds__(256) void k_zero() {
    int i = blockIdx.x * blockDim.x + threadIdx.x;
    if (i < N_ENT) { g_deg[i] = 0; g_cursor[i] = 0; }
}

// ---------------- proj[r,n,e] = sum_d ent[n,d] * W_R[r,d,e] ----------------
// Block: 128 threads, tile = 128 nodes x 64 cols, 4 relations per block.
// Thread tile: 8 nodes (4 float2 pairs) x 8 strided cols -> 1.0 B SMEM / MAC.
#define PROJ_NODES 128
__global__ __launch_bounds__(128) void k_proj(const float* __restrict__ ent,
                                              const float* __restrict__ WR) {
    __shared__ __align__(16) float entT[64 * PROJ_NODES];  // [k][node] 32KB
    __shared__ __align__(16) float Wsm[64 * 64];           // 16KB
    const int tid = threadIdx.x;
    const int n0  = blockIdx.x * PROJ_NODES;

    // fill entT: thread owns node `tid` -> conflict-free STS (bank = tid%32)
    {
        int n = n0 + tid;
        if (n < N_ENT) {
            const float4* er = reinterpret_cast<const float4*>(ent + (size_t)n * 64);
#pragma unroll
            for (int q = 0; q < 16; q++) {
                float4 v = er[q];
                entT[(4 * q + 0) * PROJ_NODES + tid] = v.x;
                entT[(4 * q + 1) * PROJ_NODES + tid] = v.y;
                entT[(4 * q + 2) * PROJ_NODES + tid] = v.z;
                entT[(4 * q + 3) * PROJ_NODES + tid] = v.w;
            }
        } else {
#pragma unroll
            for (int q = 0; q < 16; q++) {
                entT[(4 * q + 0) * PROJ_NODES + tid] = 0.0f;
                entT[(4 * q + 1) * PROJ_NODES + tid] = 0.0f;
                entT[(4 * q + 2) * PROJ_NODES + tid] = 0.0f;
                entT[(4 * q + 3) * PROJ_NODES + tid] = 0.0f;
            }
        }
    }

    const int cb = tid & 7;    // col group: cols cb + 8j
    const int nb = tid >> 3;   // node group: nodes nb*8 .. +7

    for (int rr = 0; rr < 4; rr++) {
        const int r = blockIdx.y * 4 + rr;
        __syncthreads();   // entT ready / previous relation's Wsm reads done
        const float* W = WR + (size_t)r * 4096;
        for (int i = tid; i < 4096; i += 128) Wsm[i] = W[i];
        __syncthreads();

        float2 acc[4][8];
#pragma unroll
        for (int p = 0; p < 4; p++)
#pragma unroll
            for (int j = 0; j < 8; j++) acc[p][j] = make_float2(0.0f, 0.0f);

#pragma unroll 4
        for (int k = 0; k < 64; k++) {
            const float4* eb = reinterpret_cast<const float4*>(&entT[k * PROJ_NODES + nb * 8]);
            float4 ea = eb[0], eb1 = eb[1];
            float2 ep[4];
            ep[0] = make_float2(ea.x, ea.y);
            ep[1] = make_float2(ea.z, ea.w);
            ep[2] = make_float2(eb1.x, eb1.y);
            ep[3] = make_float2(eb1.z, eb1.w);
#pragma unroll
            for (int j = 0; j < 8; j++) {
                float w = Wsm[k * 64 + cb + 8 * j];
                float2 w2 = make_float2(w, w);
#pragma unroll
                for (int p = 0; p < 4; p++) acc[p][j] = ffma2(ep[p], w2, acc[p][j]);
            }
        }

        float* outb = g_proj + ((size_t)r * N_ENT + n0) * 64;
#pragma unroll
        for (int p = 0; p < 4; p++) {
            int node = nb * 8 + 2 * p;
            bool ok0 = (n0 + node) < N_ENT;
            bool ok1 = (n0 + node + 1) < N_ENT;
#pragma unroll
            for (int j = 0; j < 8; j++) {
                int col = cb + 8 * j;
                if (ok0) outb[(size_t)node * 64 + col] = acc[p][j].x;
                if (ok1) outb[(size_t)(node + 1) * 64 + col] = acc[p][j].y;
            }
        }
    }
}

// ---------------- CSR build ----------------
__global__ __launch_bounds__(256) void k_count(const int* __restrict__ dst) {
    int e = blockIdx.x * blockDim.x + threadIdx.x;
    if (e < N_EDGE) atomicAdd(&g_deg[dst[e]], 1);
}

__global__ __launch_bounds__(512) void k_scan1() {
    __shared__ int sm[512];
    int i = blockIdx.x * 512 + threadIdx.x;
    int v = (i < N_ENT) ? g_deg[i] : 0;
    sm[threadIdx.x] = v;
    __syncthreads();
    for (int off = 1; off < 512; off <<= 1) {
        int t = (threadIdx.x >= off) ? sm[threadIdx.x - off] : 0;
        __syncthreads();
        sm[threadIdx.x] += t;
        __syncthreads();
    }
    if (i < N_ENT) g_incl[i] = sm[threadIdx.x];
    if (threadIdx.x == 511) g_bsum[blockIdx.x] = sm[511];
}

__global__ void k_scan2(int nb) {
    if (blockIdx.x == 0 && threadIdx.x == 0) {
        int run = 0;
        for (int b = 0; b < nb; b++) { int t = g_bsum[b]; g_bsum[b] = run; run += t; }
    }
}

__global__ __launch_bounds__(512) void k_scan3() {
    int i = blockIdx.x * blockDim.x + threadIdx.x;
    if (i < N_ENT) g_offs[i] = g_incl[i] - g_deg[i] + g_bsum[i / 512];
    if (i == 0) g_offs[N_ENT] = N_EDGE;
}

__global__ __launch_bounds__(256) void k_scatter(const int* __restrict__ src,
                                                 const int* __restrict__ dst,
                                                 const int* __restrict__ et) {
    int e = blockIdx.x * blockDim.x + threadIdx.x;
    if (e < N_EDGE) {
        int d = dst[e];
        int pos = g_offs[d] + atomicAdd(&g_cursor[d], 1);
        g_srcs[pos] = src[e];
        g_dsts[pos] = d;
        g_ets[pos]  = et[e];
    }
}

// ---------------- attention logits: warp handles 8 CSR-ordered edges ----------------
__global__ __launch_bounds__(256) void k_att(const float* __restrict__ rel) {
    int w = (blockIdx.x * blockDim.x + threadIdx.x) >> 5;
    int lane = threadIdx.x & 31;
    int base = w * 8;
    if (base >= N_EDGE) return;

    int mv = 0;
    int idx = base + (lane & 7);
    if (lane < 8)       mv = g_srcs[idx];
    else if (lane < 16) mv = g_dsts[idx];
    else if (lane < 24) mv = g_ets[idx];

    float res = 0.0f;
#pragma unroll
    for (int j = 0; j < 8; j++) {
        int s = __shfl_sync(0xffffffffu, mv, j);
        int d = __shfl_sync(0xffffffffu, mv, 8 + j);
        int r = __shfl_sync(0xffffffffu, mv, 16 + j);
        const float2* pt = reinterpret_cast<const float2*>(g_proj + ((size_t)r * N_ENT + s) * 64);
        const float2* ph = reinterpret_cast<const float2*>(g_proj + ((size_t)r * N_ENT + d) * 64);
        const float2* pr = reinterpret_cast<const float2*>(rel + (size_t)r * 64);
        float2 t = pt[lane], h = ph[lane], rr = pr[lane];
        float p = t.x * tanhf(h.x + rr.x) + t.y * tanhf(h.y + rr.y);
#pragma unroll
        for (int o = 16; o; o >>= 1) p += __shfl_xor_sync(0xffffffffu, p, o);
        if (lane == j) res = p;
    }
    if (lane < 8) g_att[base + lane] = res;   // coalesced
}

// ---------------- edge softmax by dst (warp per node, all-sequential IO) ----------------
__global__ __launch_bounds__(256) void k_softmax() {
    int n = blockIdx.x * (blockDim.x >> 5) + (threadIdx.x >> 5);
    int lane = threadIdx.x & 31;
    if (n >= N_ENT) return;
    int beg = g_offs[n], end = g_offs[n + 1];
    if (beg == end) return;
    float m = -3.4e38f;
    for (int p = beg + lane; p < end; p += 32) m = fmaxf(m, g_att[p]);
#pragma unroll
    for (int o = 16; o; o >>= 1) m = fmaxf(m, __shfl_xor_sync(0xffffffffu, m, o));
    float s = 0.0f;
    for (int p = beg + lane; p < end; p += 32) {
        float e = expf(g_att[p] - m);
        g_a[p] = e;
        s += e;
    }
#pragma unroll
    for (int o = 16; o; o >>= 1) s += __shfl_xor_sync(0xffffffffu, s, o);
    float inv = 1.0f / s;
    for (int p = beg + lane; p < end; p += 32) g_a[p] *= inv;
}

// ---------------- fused layer: agg + bi-interaction + l2norm + output ----------------
template <int L>
__global__ __launch_bounds__(256) void k_layer(const float* __restrict__ ent,
                                               const float* __restrict__ W1,
                                               const float* __restrict__ b1,
                                               const float* __restrict__ W2,
                                               const float* __restrict__ b2,
                                               float* __restrict__ out) {
    constexpr int DIN  = (L == 0) ? 64 : (L == 1) ? 64 : 32;
    constexpr int DOUT = (L == 0) ? 64 : (L == 1) ? 32 : 16;
    constexpr int CB   = (L == 0) ? 64 : (L == 1) ? 128 : 160;
    constexpr int V    = DIN / 32;
    constexpr int OV   = (DOUT + 31) / 32;
    const float* hin = (L == 0) ? ent : (L == 1) ? g_h1 : g_h2;
    float* hout      = (L == 0) ? g_h1 : (L == 1) ? g_h2 : nullptr;

    __shared__ float2 Wint[DIN * DOUT];
    __shared__ float2 bint[DOUT];
    for (int i = threadIdx.x; i < DIN * DOUT; i += blockDim.x)
        Wint[i] = make_float2(W1[i], W2[i]);
    if (threadIdx.x < DOUT)
        bint[threadIdx.x] = make_float2(b1[threadIdx.x], b2[threadIdx.x]);
    __syncthreads();

    int lane = threadIdx.x & 31;
    int n = blockIdx.x * (blockDim.x >> 5) + (threadIdx.x >> 5);
    if (n >= N_ENT) return;

    float hv[V], nv[V];
#pragma unroll
    for (int v = 0; v < V; v++) {
        hv[v] = hin[(size_t)n * DIN + lane + 32 * v];
        nv[v] = 0.0f;
    }
    int beg = g_offs[n], end = g_offs[n + 1];
    for (int p = beg; p < end; p++) {
        float c = g_a[p];
        const float* hs = hin + (size_t)g_srcs[p] * DIN;
#pragma unroll
        for (int v = 0; v < V; v++) nv[v] += c * hs[lane + 32 * v];
    }

    float sv1[V], sv2[V];
#pragma unroll
    for (int v = 0; v < V; v++) { sv1[v] = hv[v] + nv[v]; sv2[v] = hv[v] * nv[v]; }

    float2 acc[OV];
#pragma unroll
    for (int o = 0; o < OV; o++) acc[o] = make_float2(0.0f, 0.0f);
#pragma unroll
    for (int i = 0; i < DIN; i++) {
        float x1 = __shfl_sync(0xffffffffu, sv1[i >> 5], i & 31);
        float x2 = __shfl_sync(0xffffffffu, sv2[i >> 5], i & 31);
        float2 xp = make_float2(x1, x2);
#pragma unroll
        for (int o = 0; o < OV; o++) {
            int j = lane + 32 * o;
            if (j < DOUT) acc[o] = ffma2(xp, Wint[i * DOUT + j], acc[o]);
        }
    }

    float y[OV];
    float ss = 0.0f;
#pragma unroll
    for (int o = 0; o < OV; o++) {
        int j = lane + 32 * o;
        if (j < DOUT) {
            float y1 = acc[o].x + bint[j].x; y1 = (y1 > 0.0f) ? y1 : 0.01f * y1;
            float y2 = acc[o].y + bint[j].y; y2 = (y2 > 0.0f) ? y2 : 0.01f * y2;
            y[o] = y1 + y2;
            ss += y[o] * y[o];
        }
    }
#pragma unroll
    for (int o = 16; o; o >>= 1) ss += __shfl_xor_sync(0xffffffffu, ss, o);
    float inv = 1.0f / fmaxf(sqrtf(ss), 1e-12f);

#pragma unroll
    for (int o = 0; o < OV; o++) {
        int j = lane + 32 * o;
        if (j < DOUT) {
            if (hout) hout[(size_t)n * DOUT + j] = y[o];
            out[(size_t)n * DOUT_TOTAL + CB + j] = y[o] * inv;
        }
    }
    if (L == 0) {
#pragma unroll
        for (int v = 0; v < V; v++)
            out[(size_t)n * DOUT_TOTAL + lane + 32 * v] = hv[v];
    }
}

// ---------------- launch ----------------
extern "C" void kernel_launch(void* const* d_in, const int* in_sizes, int n_in,
                              void* d_out, int out_size) {
    const float* ent  = (const float*)d_in[0];
    const float* rel  = (const float*)d_in[1];
    const float* WR   = (const float*)d_in[2];
    const float* W1_0 = (const float*)d_in[3];
    const float* b1_0 = (const float*)d_in[4];
    const float* W2_0 = (const float*)d_in[5];
    const float* b2_0 = (const float*)d_in[6];
    const float* W1_1 = (const float*)d_in[7];
    const float* b1_1 = (const float*)d_in[8];
    const float* W2_1 = (const float*)d_in[9];
    const float* b2_1 = (const float*)d_in[10];
    const float* W1_2 = (const float*)d_in[11];
    const float* b1_2 = (const float*)d_in[12];
    const float* W2_2 = (const float*)d_in[13];
    const float* b2_2 = (const float*)d_in[14];
    const int* src = (const int*)d_in[15];
    const int* dst = (const int*)d_in[16];
    const int* et  = (const int*)d_in[17];
    float* out = (float*)d_out;

    const int NB_SCAN = (N_ENT + 511) / 512;   // 98

    k_zero<<<(N_ENT + 255) / 256, 256>>>();
    k_count<<<(N_EDGE + 255) / 256, 256>>>(dst);
    k_scan1<<<NB_SCAN, 512>>>();
    k_proj<<<dim3((N_ENT + PROJ_NODES - 1) / PROJ_NODES, N_REL / 4), 128>>>(ent, WR);
    k_scan2<<<1, 32>>>(NB_SCAN);
    k_scan3<<<(N_ENT + 511) / 512, 512>>>();
    k_scatter<<<(N_EDGE + 255) / 256, 256>>>(src, dst, et);
    k_att<<<(N_EDGE / 8 + 7) / 8, 256>>>(rel);
    k_softmax<<<(N_ENT + 7) / 8, 256>>>();
    k_layer<0><<<(N_ENT + 7) / 8, 256>>>(ent, W1_0, b1_0, W2_0, b2_0, out);
    k_layer<1><<<(N_ENT + 7) / 8, 256>>>(ent, W1_1, b1_1, W2_1, b2_1, out);
    k_layer<2><<<(N_ENT + 7) / 8, 256>>>(ent, W1_2, b1_2, W2_2, b2_2, out);
}